// round 3
// baseline (speedup 1.0000x reference)
#include <cuda_runtime.h>
#include <cstdint>

#define BB 32
#define TT 8192
#define DD 256
#define UU 128

#define MT 128          // CTA row tile
#define KC 32           // K chunk
#define AST 36          // A smem row stride (floats), pad for conflict-free frags
#define BST 36          // B smem row stride

// Scratch (static device globals — allocation-free)
__device__ float g_hq[BB * UU];
__device__ float g_scores[BB * TT];
__device__ float g_partials[BB * 16 * DD];

// ---------------------------------------------------------------------------
// helpers
// ---------------------------------------------------------------------------
__device__ __forceinline__ uint32_t to_tf32(float x) {
    uint32_t r;
    asm("cvt.rna.tf32.f32 %0, %1;" : "=r"(r) : "f"(x));
    return r;
}

__device__ __forceinline__ void mma_tf32(float c[4],
                                         uint32_t a0, uint32_t a1, uint32_t a2, uint32_t a3,
                                         uint32_t b0, uint32_t b1) {
    asm volatile(
        "mma.sync.aligned.m16n8k8.row.col.f32.tf32.tf32.f32 "
        "{%0,%1,%2,%3}, {%4,%5,%6,%7}, {%8,%9}, {%0,%1,%2,%3};"
        : "+f"(c[0]), "+f"(c[1]), "+f"(c[2]), "+f"(c[3])
        : "r"(a0), "r"(a1), "r"(a2), "r"(a3), "r"(b0), "r"(b1));
}

// exact tanh via e^{2x}: tanh(x) = 1 - 2/(e^{2x}+1).  ~1e-6 abs error, handles +-inf.
__device__ __forceinline__ float tanh_acc(float x) {
    float e = __expf(2.0f * x);
    return 1.0f - __fdividef(2.0f, e + 1.0f);
}

// ---------------------------------------------------------------------------
// kernel 0: hq[b][u] = relu(query[b] @ W2[:,u] + W2b[u])
// ---------------------------------------------------------------------------
__global__ void hq_kernel(const float* __restrict__ query,
                          const float* __restrict__ W2,
                          const float* __restrict__ W2b) {
    int b = blockIdx.x;
    int u = threadIdx.x;
    const float* q = query + b * DD;
    float acc = 0.0f;
#pragma unroll 8
    for (int d = 0; d < DD; d++) acc += q[d] * W2[d * UU + u];
    acc += W2b[u];
    g_hq[b * UU + u] = fmaxf(acc, 0.0f);
}

// ---------------------------------------------------------------------------
// kernel 1: scores. CTA tile 128 rows x 128 units, tf32 mma, fused epilogue.
// ---------------------------------------------------------------------------
__global__ __launch_bounds__(256, 2) void scores_kernel(
    const float* __restrict__ values,
    const float* __restrict__ W1,
    const float* __restrict__ W1b,
    const float* __restrict__ Vk,
    const float* __restrict__ Vb) {
    __shared__ float As[MT * AST];   // [row][k]
    __shared__ float Bs[UU * BST];   // [n][k]  (W1 chunk transposed)
    __shared__ float s_hq[UU], s_b1[UU], s_v[UU];

    const int tid  = threadIdx.x;
    const int w    = tid >> 5;
    const int lane = tid & 31;
    const int g    = lane >> 2;
    const int tg   = lane & 3;
    const int row_base = blockIdx.x * MT;
    const int b = row_base >> 13;            // T = 8192, MT divides T

    if (tid < UU) {
        s_hq[tid] = g_hq[b * UU + tid];
        s_b1[tid] = W1b[tid];
        s_v[tid]  = Vk[tid];
    }

    float acc[16][4];
#pragma unroll
    for (int j = 0; j < 16; j++) {
        acc[j][0] = 0.f; acc[j][1] = 0.f; acc[j][2] = 0.f; acc[j][3] = 0.f;
    }

    for (int kc = 0; kc < DD / KC; kc++) {
        const int kb = kc * KC;
        // --- stage A tile: 128 rows x 32 k (float4, tf32-converted) ---
#pragma unroll
        for (int i = 0; i < 4; i++) {
            int idx = tid + i * 256;           // float4 index, 1024 total
            int r   = idx >> 3;
            int c4  = (idx & 7) * 4;
            float4 v = *reinterpret_cast<const float4*>(
                values + (row_base + r) * DD + kb + c4);
            uint4 t;
            t.x = to_tf32(v.x); t.y = to_tf32(v.y);
            t.z = to_tf32(v.z); t.w = to_tf32(v.w);
            *reinterpret_cast<uint4*>(As + r * AST + c4) = t;
        }
        // --- stage B tile transposed: Bs[n][k], 32 k x 128 n ---
#pragma unroll
        for (int i = 0; i < 16; i++) {
            int idx = tid + i * 256;           // 4096 total
            int n = idx & 127;
            int k = idx >> 7;
            float v = W1[(kb + k) * UU + n];
            *reinterpret_cast<uint32_t*>(Bs + n * BST + k) = to_tf32(v);
        }
        __syncthreads();

#pragma unroll
        for (int ks = 0; ks < 4; ks++) {
            const int k0 = ks * 8;
            const float* ap = As + (16 * w + g) * AST + k0 + tg;
            uint32_t a0 = __float_as_uint(ap[0]);
            uint32_t a1 = __float_as_uint(ap[8 * AST]);
            uint32_t a2 = __float_as_uint(ap[4]);
            uint32_t a3 = __float_as_uint(ap[8 * AST + 4]);
#pragma unroll
            for (int j = 0; j < 16; j++) {
                const float* bp = Bs + (8 * j + g) * BST + k0 + tg;
                uint32_t b0 = __float_as_uint(bp[0]);
                uint32_t b1 = __float_as_uint(bp[4]);
                mma_tf32(acc[j], a0, a1, a2, a3, b0, b1);
            }
        }
        __syncthreads();
    }

    // --- epilogue: score = sum_u V[u]*tanh(relu(acc+b1)+hq) , + Vb ---
    float sg = 0.f, sg8 = 0.f;
#pragma unroll
    for (int j = 0; j < 16; j++) {
        int c0 = 8 * j + 2 * tg;
        int c1 = c0 + 1;
        float v0 = s_v[c0], v1 = s_v[c1];
        float h0 = s_hq[c0], h1 = s_hq[c1];
        float b0 = s_b1[c0], b1f = s_b1[c1];
        sg  += v0 * tanh_acc(fmaxf(acc[j][0] + b0, 0.f) + h0);
        sg  += v1 * tanh_acc(fmaxf(acc[j][1] + b1f, 0.f) + h1);
        sg8 += v0 * tanh_acc(fmaxf(acc[j][2] + b0, 0.f) + h0);
        sg8 += v1 * tanh_acc(fmaxf(acc[j][3] + b1f, 0.f) + h1);
    }
    // reduce over the quad (tg = 0..3)
    sg  += __shfl_xor_sync(0xffffffffu, sg, 1);
    sg  += __shfl_xor_sync(0xffffffffu, sg, 2);
    sg8 += __shfl_xor_sync(0xffffffffu, sg8, 1);
    sg8 += __shfl_xor_sync(0xffffffffu, sg8, 2);
    if (tg == 0) {
        float vb = Vb[0];
        g_scores[row_base + 16 * w + g]     = sg + vb;
        g_scores[row_base + 16 * w + g + 8] = sg8 + vb;
    }
}

// ---------------------------------------------------------------------------
// kernel 2: softmax over T per batch, writes normalized weights to d_out
// ---------------------------------------------------------------------------
__global__ void softmax_kernel(float* __restrict__ w_out) {
    __shared__ float red[8];
    const int b = blockIdx.x;
    const int tid = threadIdx.x;
    const float* s = g_scores + b * TT;
    float* wo = w_out + b * TT;

    float m = -3.4e38f;
    for (int t = tid; t < TT; t += 256) m = fmaxf(m, s[t]);
#pragma unroll
    for (int o = 16; o > 0; o >>= 1) m = fmaxf(m, __shfl_xor_sync(0xffffffffu, m, o));
    if ((tid & 31) == 0) red[tid >> 5] = m;
    __syncthreads();
    float mx = red[0];
#pragma unroll
    for (int i = 1; i < 8; i++) mx = fmaxf(mx, red[i]);
    __syncthreads();

    float sum = 0.f;
    for (int t = tid; t < TT; t += 256) {
        float e = __expf(s[t] - mx);
        wo[t] = e;
        sum += e;
    }
#pragma unroll
    for (int o = 16; o > 0; o >>= 1) sum += __shfl_xor_sync(0xffffffffu, sum, o);
    if ((tid & 31) == 0) red[tid >> 5] = sum;
    __syncthreads();
    float tot = 0.f;
#pragma unroll
    for (int i = 0; i < 8; i++) tot += red[i];
    float inv = 1.0f / tot;
    for (int t = tid; t < TT; t += 256) wo[t] *= inv;
}

// ---------------------------------------------------------------------------
// kernel 3: context partials: 512 blocks, each (b, chunk of 512 t-rows)
// ---------------------------------------------------------------------------
__global__ __launch_bounds__(256) void ctx_partial_kernel(
    const float* __restrict__ values, const float* __restrict__ wts) {
    __shared__ float ws[512];
    const int bid = blockIdx.x;          // 0..511
    const int b = bid >> 4;
    const int t0 = (bid & 15) * 512;
    const int d = threadIdx.x;

    for (int i = threadIdx.x; i < 512; i += 256) ws[i] = wts[b * TT + t0 + i];
    __syncthreads();

    const float* vp = values + (b * TT + t0) * DD + d;
    float acc = 0.f;
#pragma unroll 8
    for (int i = 0; i < 512; i++) acc += ws[i] * vp[i * DD];
    g_partials[bid * DD + d] = acc;
}

// ---------------------------------------------------------------------------
// kernel 4: final context reduction -> d_out[0 : B*D]
// ---------------------------------------------------------------------------
__global__ void ctx_final_kernel(float* __restrict__ ctx) {
    const int b = blockIdx.x;
    const int d = threadIdx.x;
    float acc = 0.f;
#pragma unroll
    for (int c = 0; c < 16; c++) acc += g_partials[(b * 16 + c) * DD + d];
    ctx[b * DD + d] = acc;
}

// ---------------------------------------------------------------------------
extern "C" void kernel_launch(void* const* d_in, const int* in_sizes, int n_in,
                              void* d_out, int out_size) {
    const float* query = (const float*)d_in[0];
    const float* values = (const float*)d_in[1];
    const float* W1 = (const float*)d_in[2];
    const float* W1b = (const float*)d_in[3];
    const float* W2 = (const float*)d_in[4];
    const float* W2b = (const float*)d_in[5];
    const float* Vk = (const float*)d_in[6];
    const float* Vb = (const float*)d_in[7];

    float* out = (float*)d_out;
    float* ctx = out;              // [B, D]
    float* wts = out + BB * DD;    // [B, T, 1]

    hq_kernel<<<BB, UU>>>(query, W2, W2b);
    scores_kernel<<<(BB * TT) / MT, 256>>>(values, W1, W1b, Vk, Vb);
    softmax_kernel<<<BB, 256>>>(wts);
    ctx_partial_kernel<<<BB * 16, 256>>>(values, wts);
    ctx_final_kernel<<<BB, DD>>>(ctx);
}